// round 1
// baseline (speedup 1.0000x reference)
#include <cuda_runtime.h>
#include <cuda_bf16.h>

// ---------------------------------------------------------------------------
// Shapes (fixed by the problem)
// ---------------------------------------------------------------------------
#define B_  16
#define N_  4096
#define C_  768
#define L_  16
#define H_  12
#define HD_ 64
#define STEPS_ 3

// ---------------------------------------------------------------------------
// Scratch (__device__ globals — no allocation allowed in kernel_launch)
// ---------------------------------------------------------------------------
__device__ float g_k_scr[(size_t)B_ * N_ * C_];   // 201 MB: k = x @ Wk^T, layout [B*N, C]
__device__ float g_q0_scr[L_ * C_];               // q0 = query @ Wq^T, [L, C]
__device__ float g_qf_scr[B_ * L_ * C_];          // hopfield output, [B, L, C]
__device__ float g_tmp_scr[B_ * L_ * C_];         // after Wv projection

// ---------------------------------------------------------------------------
// Kernel 1: big SGEMM  C[M,N] = A[M,K] * B[N,K]^T   (fp32, 128x128x8 tiles)
// M,N multiples of 128; K multiple of 8.
// ---------------------------------------------------------------------------
__global__ void __launch_bounds__(256) sgemm_nt_kernel(
    const float* __restrict__ A, const float* __restrict__ Bm,
    float* __restrict__ C, int M, int N, int K)
{
    __shared__ __align__(16) float As[8 * 128];
    __shared__ __align__(16) float Bs[8 * 128];

    const int t  = threadIdx.x;
    const int m0 = blockIdx.y * 128;
    const int n0 = blockIdx.x * 128;
    const int tx = t & 15;        // 0..15 -> 8 cols each
    const int ty = t >> 4;        // 0..15 -> 8 rows each

    const int lrow = t >> 1;       // 0..127
    const int lc4  = (t & 1) * 4;  // 0 or 4

    const float* Ap = A + (long)(m0 + lrow) * K + lc4;
    const float* Bp = Bm + (long)(n0 + lrow) * K + lc4;

    float acc[8][8];
#pragma unroll
    for (int i = 0; i < 8; i++)
#pragma unroll
        for (int j = 0; j < 8; j++) acc[i][j] = 0.0f;

    for (int k0 = 0; k0 < K; k0 += 8) {
        float4 av = *(const float4*)(Ap + k0);
        float4 bv = *(const float4*)(Bp + k0);
        __syncthreads();
        As[(lc4 + 0) * 128 + lrow] = av.x;
        As[(lc4 + 1) * 128 + lrow] = av.y;
        As[(lc4 + 2) * 128 + lrow] = av.z;
        As[(lc4 + 3) * 128 + lrow] = av.w;
        Bs[(lc4 + 0) * 128 + lrow] = bv.x;
        Bs[(lc4 + 1) * 128 + lrow] = bv.y;
        Bs[(lc4 + 2) * 128 + lrow] = bv.z;
        Bs[(lc4 + 3) * 128 + lrow] = bv.w;
        __syncthreads();

#pragma unroll
        for (int kk = 0; kk < 8; kk++) {
            float ra[8], rb[8];
            float4 a0 = *(const float4*)&As[kk * 128 + ty * 8 + 0];
            float4 a1 = *(const float4*)&As[kk * 128 + ty * 8 + 4];
            float4 b0 = *(const float4*)&Bs[kk * 128 + tx * 8 + 0];
            float4 b1 = *(const float4*)&Bs[kk * 128 + tx * 8 + 4];
            ra[0]=a0.x; ra[1]=a0.y; ra[2]=a0.z; ra[3]=a0.w;
            ra[4]=a1.x; ra[5]=a1.y; ra[6]=a1.z; ra[7]=a1.w;
            rb[0]=b0.x; rb[1]=b0.y; rb[2]=b0.z; rb[3]=b0.w;
            rb[4]=b1.x; rb[5]=b1.y; rb[6]=b1.z; rb[7]=b1.w;
#pragma unroll
            for (int i = 0; i < 8; i++)
#pragma unroll
                for (int j = 0; j < 8; j++)
                    acc[i][j] = fmaf(ra[i], rb[j], acc[i][j]);
        }
    }

#pragma unroll
    for (int i = 0; i < 8; i++) {
        float* cp = C + (long)(m0 + ty * 8 + i) * N + n0 + tx * 8;
        float4 o0 = make_float4(acc[i][0], acc[i][1], acc[i][2], acc[i][3]);
        float4 o1 = make_float4(acc[i][4], acc[i][5], acc[i][6], acc[i][7]);
        *(float4*)(cp + 0) = o0;
        *(float4*)(cp + 4) = o1;
    }
}

// ---------------------------------------------------------------------------
// Kernel 2: small GEMM  C[M,N] = A[M,K]*B[N,K]^T (+bias)
// Tiles: BM=16, BN=64, BK=16; M mult of 16, N mult of 64, K mult of 16.
// ---------------------------------------------------------------------------
__global__ void __launch_bounds__(256) small_gemm_nt(
    const float* __restrict__ A, const float* __restrict__ Bm,
    const float* __restrict__ bias, float* __restrict__ C,
    int M, int N, int K)
{
    __shared__ float AsT[16][17];
    __shared__ float BsT[16][65];

    const int t  = threadIdx.x;
    const int n0 = blockIdx.x * 64;
    const int m0 = blockIdx.y * 16;
    const int r0 = t >> 6;   // 0..3 (rows r0, r0+4, r0+8, r0+12)
    const int c  = t & 63;

    float acc[4] = {0.f, 0.f, 0.f, 0.f};

    for (int k0 = 0; k0 < K; k0 += 16) {
        __syncthreads();
        {   // A tile 16x16 -> transposed
            int mm = t >> 4, kk = t & 15;
            AsT[kk][mm] = A[(long)(m0 + mm) * K + k0 + kk];
        }
        {   // B tile 64x16 -> transposed (float4 per thread)
            int nn = t >> 2, k4 = (t & 3) * 4;
            float4 v = *(const float4*)&Bm[(long)(n0 + nn) * K + k0 + k4];
            BsT[k4 + 0][nn] = v.x;
            BsT[k4 + 1][nn] = v.y;
            BsT[k4 + 2][nn] = v.z;
            BsT[k4 + 3][nn] = v.w;
        }
        __syncthreads();
#pragma unroll
        for (int kk = 0; kk < 16; kk++) {
            float bb = BsT[kk][c];
            acc[0] = fmaf(AsT[kk][r0 +  0], bb, acc[0]);
            acc[1] = fmaf(AsT[kk][r0 +  4], bb, acc[1]);
            acc[2] = fmaf(AsT[kk][r0 +  8], bb, acc[2]);
            acc[3] = fmaf(AsT[kk][r0 + 12], bb, acc[3]);
        }
    }
    float bv = bias ? bias[n0 + c] : 0.0f;
#pragma unroll
    for (int i = 0; i < 4; i++)
        C[(long)(m0 + r0 + 4 * i) * N + n0 + c] = acc[i] + bv;
}

// ---------------------------------------------------------------------------
// Kernel 3: fused 3-step Hopfield attention with softmax_1
//   one block per (b, h); 256 threads = 8 warps; each warp owns 16 of the 128
//   key columns of each N-tile. Per lane: l = lane/2, d-half = (lane&1)*32.
//   softmax_1: denom includes exp(-m), m clamped at 0 (exactly like reference).
// ---------------------------------------------------------------------------
#define TN_ 128
#define NWARP_ 8

__global__ void __launch_bounds__(256) hopfield_kernel(
    const float* __restrict__ q0, const float* __restrict__ kmat,
    float* __restrict__ qout)
{
    __shared__ __align__(16) float ks[TN_ * HD_];   // 32 KB, reused as acc-combine buffer
    __shared__ __align__(16) float qs[L_ * HD_];    // 4 KB
    __shared__ float mw[NWARP_][L_];
    __shared__ float zw[NWARP_][L_];
    __shared__ float Mg[L_];
    __shared__ float Zg[L_];

    const int t    = threadIdx.x;
    const int bh   = blockIdx.x;
    const int b    = bh / H_;
    const int h    = bh % H_;
    const int warp = t >> 5;
    const int lane = t & 31;
    const int l     = lane >> 1;
    const int dbase = (lane & 1) * 32;
    const float scale = 0.125f;   // 64^-0.5

    // init q state from q0 (shared across batch)
    for (int i = t; i < L_ * HD_; i += 256) {
        int ll = i >> 6, dd = i & 63;
        qs[i] = q0[ll * C_ + h * HD_ + dd];
    }
    __syncthreads();

    const float* kbase = kmat + (long)b * N_ * C_ + h * HD_;

    for (int step = 0; step < STEPS_; step++) {
        float qreg[32];
#pragma unroll
        for (int i = 0; i < 8; i++) {
            float4 v = *(const float4*)&qs[l * HD_ + dbase + i * 4];
            qreg[i*4+0] = v.x * scale; qreg[i*4+1] = v.y * scale;
            qreg[i*4+2] = v.z * scale; qreg[i*4+3] = v.w * scale;
        }
        float m = -1e30f, Z = 0.0f;
        float acc[32];
#pragma unroll
        for (int i = 0; i < 32; i++) acc[i] = 0.0f;

        for (int tile = 0; tile < N_ / TN_; tile++) {
            __syncthreads();
            // load k tile [128, 64] (coalesced float4)
#pragma unroll
            for (int i = 0; i < 8; i++) {
                int idx = t + i * 256;           // float4 index, 0..2047
                int row = idx >> 4, c4 = idx & 15;
                float4 v = *(const float4*)&kbase[(long)(tile * TN_ + row) * C_ + c4 * 4];
                *(float4*)&ks[row * HD_ + c4 * 4] = v;
            }
            __syncthreads();

            // phase 1: scores for this warp's 16 columns
            float s[16];
#pragma unroll
            for (int jj = 0; jj < 16; jj++) {
                const float* kp = &ks[(warp * 16 + jj) * HD_ + dbase];
                float partial = 0.0f;
#pragma unroll
                for (int i = 0; i < 8; i++) {
                    float4 kv = *(const float4*)&kp[i * 4];
                    partial = fmaf(qreg[i*4+0], kv.x, partial);
                    partial = fmaf(qreg[i*4+1], kv.y, partial);
                    partial = fmaf(qreg[i*4+2], kv.z, partial);
                    partial = fmaf(qreg[i*4+3], kv.w, partial);
                }
                s[jj] = partial + __shfl_xor_sync(0xffffffffu, partial, 1);
            }
            // tile max + rescale
            float tm = s[0];
#pragma unroll
            for (int jj = 1; jj < 16; jj++) tm = fmaxf(tm, s[jj]);
            float Mn = fmaxf(m, tm);
            float sc = __expf(m - Mn);
            Z *= sc;
#pragma unroll
            for (int i = 0; i < 32; i++) acc[i] *= sc;
            // phase 2: weighted accumulate
#pragma unroll
            for (int jj = 0; jj < 16; jj++) {
                float p = __expf(s[jj] - Mn);
                Z += p;
                const float* kp = &ks[(warp * 16 + jj) * HD_ + dbase];
#pragma unroll
                for (int i = 0; i < 8; i++) {
                    float4 kv = *(const float4*)&kp[i * 4];
                    acc[i*4+0] = fmaf(p, kv.x, acc[i*4+0]);
                    acc[i*4+1] = fmaf(p, kv.y, acc[i*4+1]);
                    acc[i*4+2] = fmaf(p, kv.z, acc[i*4+2]);
                    acc[i*4+3] = fmaf(p, kv.w, acc[i*4+3]);
                }
            }
            m = Mn;
        }

        // cross-warp combine (flash-style), with the softmax_1 "+1" term
        if ((lane & 1) == 0) { mw[warp][l] = m; zw[warp][l] = Z; }
        __syncthreads();
        if (t < L_) {
            float M = 0.0f;    // clamp at 0 (reference: m = max(max a, 0))
#pragma unroll
            for (int w = 0; w < NWARP_; w++) M = fmaxf(M, mw[w][t]);
            Mg[t] = M;
            float Zt = __expf(-M);   // the phantom logit-0 term
#pragma unroll
            for (int w = 0; w < NWARP_; w++)
                Zt += zw[w][t] * __expf(mw[w][t] - M);
            Zg[t] = Zt;
        }
        __syncthreads();
        // write own scaled acc into ks (reused as [warp][l][d])
        {
            float f = __expf(m - Mg[l]);
#pragma unroll
            for (int i = 0; i < 8; i++) {
                float4 v = make_float4(acc[i*4+0]*f, acc[i*4+1]*f,
                                       acc[i*4+2]*f, acc[i*4+3]*f);
                *(float4*)&ks[warp * (L_ * HD_) + l * HD_ + dbase + i * 4] = v;
            }
        }
        __syncthreads();
        // reduce 8 warp partials -> new q
        for (int i = t; i < L_ * HD_; i += 256) {
            int ll = i >> 6;
            float sum = 0.0f;
#pragma unroll
            for (int w = 0; w < NWARP_; w++) sum += ks[w * (L_ * HD_) + i];
            qs[i] = sum / Zg[ll];
        }
        __syncthreads();
    }

    // write q to [B, L, C] layout (head-interleaved)
    for (int i = t; i < L_ * HD_; i += 256) {
        int ll = i >> 6, dd = i & 63;
        qout[((long)b * L_ + ll) * C_ + h * HD_ + dd] = qs[i];
    }
}

// ---------------------------------------------------------------------------
// Launch
// ---------------------------------------------------------------------------
extern "C" void kernel_launch(void* const* d_in, const int* in_sizes, int n_in,
                              void* d_out, int out_size)
{
    const float* x     = (const float*)d_in[0];
    const float* query = (const float*)d_in[1];
    const float* Wq    = (const float*)d_in[2];
    const float* Wk    = (const float*)d_in[3];
    const float* Wv    = (const float*)d_in[4];
    const float* Wproj = (const float*)d_in[5];
    const float* bproj = (const float*)d_in[6];
    float* out = (float*)d_out;

    float *k_scr, *q0_scr, *qf_scr, *tmp_scr;
    cudaGetSymbolAddress((void**)&k_scr,  g_k_scr);
    cudaGetSymbolAddress((void**)&q0_scr, g_q0_scr);
    cudaGetSymbolAddress((void**)&qf_scr, g_qf_scr);
    cudaGetSymbolAddress((void**)&tmp_scr, g_tmp_scr);

    // q0 = query @ Wq^T                       [16, 768]
    small_gemm_nt<<<dim3(C_ / 64, 1), 256>>>(query, Wq, nullptr, q0_scr,
                                             L_, C_, C_);
    // k = x @ Wk^T                            [65536, 768]
    sgemm_nt_kernel<<<dim3(C_ / 128, (B_ * N_) / 128), 256>>>(
        x, Wk, k_scr, B_ * N_, C_, C_);
    // 3-step Hopfield attention               [B, L, C]
    hopfield_kernel<<<B_ * H_, 256>>>(q0_scr, k_scr, qf_scr);
    // out projections: (q @ Wv^T) @ Wproj^T + b
    small_gemm_nt<<<dim3(C_ / 64, (B_ * L_) / 16), 256>>>(
        qf_scr, Wv, nullptr, tmp_scr, B_ * L_, C_, C_);
    small_gemm_nt<<<dim3(C_ / 64, (B_ * L_) / 16), 256>>>(
        tmp_scr, Wproj, bproj, out, B_ * L_, C_, C_);
}

// round 3
// speedup vs baseline: 1.2307x; 1.2307x over previous
#include <cuda_runtime.h>
#include <cuda_bf16.h>
#include <cstdint>

// ---------------------------------------------------------------------------
// Shapes (fixed by the problem)
// ---------------------------------------------------------------------------
#define B_  16
#define N_  4096
#define C_  768
#define L_  16
#define H_  12
#define HD_ 64
#define STEPS_ 3

#define MROWS_ (B_ * N_)            // 65536
#define KSEG_  3                    // hi*hi, hi*lo, lo*hi
#define BK_    32                   // k per pipeline chunk
#define CH_PER_SEG_ (C_ / BK_)      // 24
#define NCHUNK_TOT_ (KSEG_ * CH_PER_SEG_)  // 72

// ---------------------------------------------------------------------------
// Scratch (__device__ globals — no allocation allowed in kernel_launch)
// ---------------------------------------------------------------------------
__device__ __align__(16) float g_k_scr[(size_t)MROWS_ * C_];       // k = x @ Wk^T
__device__ __align__(16) __nv_bfloat16 g_xh[(size_t)MROWS_ * C_];  // row-major bf16
__device__ __align__(16) __nv_bfloat16 g_xl[(size_t)MROWS_ * C_];
__device__ __align__(16) __nv_bfloat16 g_wh[(size_t)C_ * C_];
__device__ __align__(16) __nv_bfloat16 g_wl[(size_t)C_ * C_];
__device__ float g_q0_scr[L_ * C_];
__device__ float g_qf_scr[B_ * L_ * C_];
__device__ float g_tmp_scr[B_ * L_ * C_];

// ---------------------------------------------------------------------------
// helpers
// ---------------------------------------------------------------------------
__device__ __forceinline__ uint32_t smem_u32(const void* p) {
    uint32_t a;
    asm("{ .reg .u64 t; cvta.to.shared.u64 t, %1; cvt.u32.u64 %0, t; }" : "=r"(a) : "l"(p));
    return a;
}
__device__ __forceinline__ void cpa16(uint32_t dst, const void* src) {
    asm volatile("cp.async.cg.shared.global [%0], [%1], 16;" :: "r"(dst), "l"(src));
}
#define CP_COMMIT() asm volatile("cp.async.commit_group;" ::: "memory")
#define CP_WAIT1()  asm volatile("cp.async.wait_group 1;" ::: "memory")

__device__ __forceinline__ void ldsm_x4(uint32_t* r, uint32_t addr) {
    asm volatile("ldmatrix.sync.aligned.m8n8.x4.shared.b16 {%0,%1,%2,%3}, [%4];"
                 : "=r"(r[0]), "=r"(r[1]), "=r"(r[2]), "=r"(r[3]) : "r"(addr));
}
__device__ __forceinline__ void ldsm_x2(uint32_t* r, uint32_t addr) {
    asm volatile("ldmatrix.sync.aligned.m8n8.x2.shared.b16 {%0,%1}, [%2];"
                 : "=r"(r[0]), "=r"(r[1]) : "r"(addr));
}
__device__ __forceinline__ void mma_bf16(float* d, const uint32_t* a, const uint32_t* b) {
    asm volatile(
        "mma.sync.aligned.m16n8k16.row.col.f32.bf16.bf16.f32 "
        "{%0,%1,%2,%3}, {%4,%5,%6,%7}, {%8,%9}, {%0,%1,%2,%3};"
        : "+f"(d[0]), "+f"(d[1]), "+f"(d[2]), "+f"(d[3])
        : "r"(a[0]), "r"(a[1]), "r"(a[2]), "r"(a[3]), "r"(b[0]), "r"(b[1]));
}

// ---------------------------------------------------------------------------
// Kernel A: split fp32 -> (hi, lo) bf16, plain row-major
// ---------------------------------------------------------------------------
__global__ void __launch_bounds__(256) convert_split_kernel(
    const float* __restrict__ src, __nv_bfloat16* __restrict__ hi,
    __nv_bfloat16* __restrict__ lo, int nchunks)
{
    int idx = blockIdx.x * 256 + threadIdx.x;
    if (idx >= nchunks) return;
    size_t e = (size_t)idx * 8;

    const float4* p = (const float4*)(src + e);
    float4 a = p[0], b = p[1];
    float v[8] = {a.x, a.y, a.z, a.w, b.x, b.y, b.z, b.w};

    uint32_t hp[4], lp[4];
#pragma unroll
    for (int i = 0; i < 4; i++) {
        __nv_bfloat16 h0 = __float2bfloat16(v[2*i]);
        __nv_bfloat16 h1 = __float2bfloat16(v[2*i+1]);
        __nv_bfloat16 l0 = __float2bfloat16(v[2*i]   - __bfloat162float(h0));
        __nv_bfloat16 l1 = __float2bfloat16(v[2*i+1] - __bfloat162float(h1));
        hp[i] = (uint32_t)__bfloat16_as_ushort(h0) | ((uint32_t)__bfloat16_as_ushort(h1) << 16);
        lp[i] = (uint32_t)__bfloat16_as_ushort(l0) | ((uint32_t)__bfloat16_as_ushort(l1) << 16);
    }
    *(uint4*)(hi + e) = make_uint4(hp[0], hp[1], hp[2], hp[3]);
    *(uint4*)(lo + e) = make_uint4(lp[0], lp[1], lp[2], lp[3]);
}

// ---------------------------------------------------------------------------
// Kernel B: HMMA GEMM  out[65536, 768] = Xsplit @ Wsplit^T  (K = 3*768)
// CTA 128x128, 8 warps (2x4) of 64x32, BK=32, 3-stage cp.async pipeline.
// smem rows padded to 80B -> conflict-free ldmatrix.
// ---------------------------------------------------------------------------
#define ROWB_ 80                       // bytes per smem row (32 bf16 + 8 pad)
#define TILEB_ (128 * ROWB_)           // 10240 B per operand tile
#define STAGEB_ (2 * TILEB_)           // 20480 B per stage
#define NSTG_ 3
#define GEMM_SMEM_REQ (NSTG_ * STAGEB_)  // 61440

__device__ __forceinline__ void load_tile(
    uint32_t aS, uint32_t bS, const char* Aseg, const char* Bseg,
    int mt, int nt, int kk, int tid)
{
#pragma unroll
    for (int i = 0; i < 2; i++) {
        int idx = tid + i * 256;           // 0..511
        int row = idx >> 2, c = idx & 3;   // 128 rows x 4 x 16B
        cpa16(aS + row * ROWB_ + c * 16,
              Aseg + ((size_t)(mt * 128 + row) * C_ + kk + c * 8) * 2);
    }
#pragma unroll
    for (int i = 0; i < 2; i++) {
        int idx = tid + i * 256;
        int row = idx >> 2, c = idx & 3;
        cpa16(bS + row * ROWB_ + c * 16,
              Bseg + ((size_t)(nt * 128 + row) * C_ + kk + c * 8) * 2);
    }
}

__global__ void __launch_bounds__(256) k_gemm_mma(
    const __nv_bfloat16* __restrict__ xh, const __nv_bfloat16* __restrict__ xl,
    const __nv_bfloat16* __restrict__ wh, const __nv_bfloat16* __restrict__ wl,
    float* __restrict__ out)
{
    extern __shared__ char dsm[];
    const uint32_t sbase = smem_u32(dsm);

    const int tid  = threadIdx.x;
    const int lane = tid & 31;
    const int warp = tid >> 5;
    const int wm   = warp >> 2;      // 0..1
    const int wn   = warp & 3;       // 0..3
    const int nt   = blockIdx.x;
    const int mt   = blockIdx.y;

    const char* Asrc[KSEG_] = {(const char*)xh, (const char*)xh, (const char*)xl};
    const char* Bsrc[KSEG_] = {(const char*)wh, (const char*)wl, (const char*)wh};

    float acc[4][4][4];
#pragma unroll
    for (int mi = 0; mi < 4; mi++)
#pragma unroll
        for (int ni = 0; ni < 4; ni++)
#pragma unroll
            for (int i = 0; i < 4; i++) acc[mi][ni][i] = 0.0f;

    // prologue: stages 0,1
#pragma unroll
    for (int s = 0; s < NSTG_ - 1; s++) {
        load_tile(sbase + s * STAGEB_, sbase + s * STAGEB_ + TILEB_,
                  Asrc[0], Bsrc[0], mt, nt, s * BK_, tid);
        CP_COMMIT();
    }

    // precomputed ldmatrix lane offsets
    const uint32_t a_lane_off = (uint32_t)((lane & 15) * ROWB_ + (lane >> 4) * 16);
    const uint32_t b_lane_off = (uint32_t)((lane & 7) * ROWB_ + ((lane >> 3) & 1) * 16);

    for (int kc = 0; kc < NCHUNK_TOT_; kc++) {
        CP_WAIT1();
        __syncthreads();

        int pf = kc + NSTG_ - 1;
        if (pf < NCHUNK_TOT_) {
            int seg = pf / CH_PER_SEG_;
            int kk  = (pf % CH_PER_SEG_) * BK_;
            int s   = pf % NSTG_;
            load_tile(sbase + s * STAGEB_, sbase + s * STAGEB_ + TILEB_,
                      Asrc[seg], Bsrc[seg], mt, nt, kk, tid);
        }
        CP_COMMIT();

        const uint32_t aS = sbase + (kc % NSTG_) * STAGEB_;
        const uint32_t bS = aS + TILEB_;
#pragma unroll
        for (int h = 0; h < 2; h++) {
            uint32_t a[4][4], b[4][2];
#pragma unroll
            for (int mi = 0; mi < 4; mi++)
                ldsm_x4(a[mi], aS + (wm * 64 + mi * 16) * ROWB_ + h * 32 + a_lane_off);
#pragma unroll
            for (int ni = 0; ni < 4; ni++)
                ldsm_x2(b[ni], bS + (wn * 32 + ni * 8) * ROWB_ + h * 32 + b_lane_off);
#pragma unroll
            for (int mi = 0; mi < 4; mi++)
#pragma unroll
                for (int ni = 0; ni < 4; ni++)
                    mma_bf16(acc[mi][ni], a[mi], b[ni]);
        }
        __syncthreads();
    }

    // epilogue: direct float2 stores (each 32B sector fully covered by 4 lanes)
#pragma unroll
    for (int mi = 0; mi < 4; mi++) {
#pragma unroll
        for (int ni = 0; ni < 4; ni++) {
            int r = mt * 128 + wm * 64 + mi * 16 + (lane >> 2);
            int c = nt * 128 + wn * 32 + ni * 8 + (lane & 3) * 2;
            float2 v0 = make_float2(acc[mi][ni][0], acc[mi][ni][1]);
            float2 v1 = make_float2(acc[mi][ni][2], acc[mi][ni][3]);
            *(float2*)&out[(size_t)r * C_ + c] = v0;
            *(float2*)&out[(size_t)(r + 8) * C_ + c] = v1;
        }
    }
}

// ---------------------------------------------------------------------------
// Kernel 2: small GEMM  C[M,N] = A[M,K]*B[N,K]^T (+bias)  (unchanged, passing)
// ---------------------------------------------------------------------------
__global__ void __launch_bounds__(256) small_gemm_nt(
    const float* __restrict__ A, const float* __restrict__ Bm,
    const float* __restrict__ bias, float* __restrict__ C,
    int M, int N, int K)
{
    __shared__ float AsT[16][17];
    __shared__ float BsT[16][65];

    const int t  = threadIdx.x;
    const int n0 = blockIdx.x * 64;
    const int m0 = blockIdx.y * 16;
    const int r0 = t >> 6;
    const int c  = t & 63;

    float acc[4] = {0.f, 0.f, 0.f, 0.f};

    for (int k0 = 0; k0 < K; k0 += 16) {
        __syncthreads();
        { int mm = t >> 4, kk = t & 15;
          AsT[kk][mm] = A[(long)(m0 + mm) * K + k0 + kk]; }
        { int nn = t >> 2, k4 = (t & 3) * 4;
          float4 v = *(const float4*)&Bm[(long)(n0 + nn) * K + k0 + k4];
          BsT[k4 + 0][nn] = v.x; BsT[k4 + 1][nn] = v.y;
          BsT[k4 + 2][nn] = v.z; BsT[k4 + 3][nn] = v.w; }
        __syncthreads();
#pragma unroll
        for (int kk = 0; kk < 16; kk++) {
            float bb = BsT[kk][c];
            acc[0] = fmaf(AsT[kk][r0 +  0], bb, acc[0]);
            acc[1] = fmaf(AsT[kk][r0 +  4], bb, acc[1]);
            acc[2] = fmaf(AsT[kk][r0 +  8], bb, acc[2]);
            acc[3] = fmaf(AsT[kk][r0 + 12], bb, acc[3]);
        }
    }
    float bv = bias ? bias[n0 + c] : 0.0f;
#pragma unroll
    for (int i = 0; i < 4; i++)
        C[(long)(m0 + r0 + 4 * i) * N + n0 + c] = acc[i] + bv;
}

// ---------------------------------------------------------------------------
// Kernel 3: fused 3-step Hopfield attention with softmax_1 (unchanged, passing)
// ---------------------------------------------------------------------------
#define TN_ 128
#define NWARP_ 8

__global__ void __launch_bounds__(256) hopfield_kernel(
    const float* __restrict__ q0, const float* __restrict__ kmat,
    float* __restrict__ qout)
{
    __shared__ __align__(16) float ks[TN_ * HD_];
    __shared__ __align__(16) float qs[L_ * HD_];
    __shared__ float mw[NWARP_][L_];
    __shared__ float zw[NWARP_][L_];
    __shared__ float Mg[L_];
    __shared__ float Zg[L_];

    const int t    = threadIdx.x;
    const int bh   = blockIdx.x;
    const int b    = bh / H_;
    const int h    = bh % H_;
    const int warp = t >> 5;
    const int lane = t & 31;
    const int l     = lane >> 1;
    const int dbase = (lane & 1) * 32;
    const float scale = 0.125f;

    for (int i = t; i < L_ * HD_; i += 256) {
        int ll = i >> 6, dd = i & 63;
        qs[i] = q0[ll * C_ + h * HD_ + dd];
    }
    __syncthreads();

    const float* kbase = kmat + (long)b * N_ * C_ + h * HD_;

    for (int step = 0; step < STEPS_; step++) {
        float qreg[32];
#pragma unroll
        for (int i = 0; i < 8; i++) {
            float4 v = *(const float4*)&qs[l * HD_ + dbase + i * 4];
            qreg[i*4+0] = v.x * scale; qreg[i*4+1] = v.y * scale;
            qreg[i*4+2] = v.z * scale; qreg[i*4+3] = v.w * scale;
        }
        float m = -1e30f, Z = 0.0f;
        float acc[32];
#pragma unroll
        for (int i = 0; i < 32; i++) acc[i] = 0.0f;

        for (int tile = 0; tile < N_ / TN_; tile++) {
            __syncthreads();
#pragma unroll
            for (int i = 0; i < 8; i++) {
                int idx = t + i * 256;
                int row = idx >> 4, c4 = idx & 15;
                float4 v = *(const float4*)&kbase[(long)(tile * TN_ + row) * C_ + c4 * 4];
                *(float4*)&ks[row * HD_ + c4 * 4] = v;
            }
            __syncthreads();

            float s[16];
#pragma unroll
            for (int jj = 0; jj < 16; jj++) {
                const float* kp = &ks[(warp * 16 + jj) * HD_ + dbase];
                float partial = 0.0f;
#pragma unroll
                for (int i = 0; i < 8; i++) {
                    float4 kv = *(const float4*)&kp[i * 4];
                    partial = fmaf(qreg[i*4+0], kv.x, partial);
                    partial = fmaf(qreg[i*4+1], kv.y, partial);
                    partial = fmaf(qreg[i*4+2], kv.z, partial);
                    partial = fmaf(qreg[i*4+3], kv.w, partial);
                }
                s[jj] = partial + __shfl_xor_sync(0xffffffffu, partial, 1);
            }
            float tm = s[0];
#pragma unroll
            for (int jj = 1; jj < 16; jj++) tm = fmaxf(tm, s[jj]);
            float Mn = fmaxf(m, tm);
            float sc = __expf(m - Mn);
            Z *= sc;
#pragma unroll
            for (int i = 0; i < 32; i++) acc[i] *= sc;
#pragma unroll
            for (int jj = 0; jj < 16; jj++) {
                float p = __expf(s[jj] - Mn);
                Z += p;
                const float* kp = &ks[(warp * 16 + jj) * HD_ + dbase];
#pragma unroll
                for (int i = 0; i < 8; i++) {
                    float4 kv = *(const float4*)&kp[i * 4];
                    acc[i*4+0] = fmaf(p, kv.x, acc[i*4+0]);
                    acc[i*4+1] = fmaf(p, kv.y, acc[i*4+1]);
                    acc[i*4+2] = fmaf(p, kv.z, acc[i*4+2]);
                    acc[i*4+3] = fmaf(p, kv.w, acc[i*4+3]);
                }
            }
            m = Mn;
        }

        if ((lane & 1) == 0) { mw[warp][l] = m; zw[warp][l] = Z; }
        __syncthreads();
        if (t < L_) {
            float M = 0.0f;
#pragma unroll
            for (int w = 0; w < NWARP_; w++) M = fmaxf(M, mw[w][t]);
            Mg[t] = M;
            float Zt = __expf(-M);
#pragma unroll
            for (int w = 0; w < NWARP_; w++)
                Zt += zw[w][t] * __expf(mw[w][t] - M);
            Zg[t] = Zt;
        }
        __syncthreads();
        {
            float f = __expf(m - Mg[l]);
#pragma unroll
            for (int i = 0; i < 8; i++) {
                float4 v = make_float4(acc[i*4+0]*f, acc[i*4+1]*f,
                                       acc[i*4+2]*f, acc[i*4+3]*f);
                *(float4*)&ks[warp * (L_ * HD_) + l * HD_ + dbase + i * 4] = v;
            }
        }
        __syncthreads();
        for (int i = t; i < L_ * HD_; i += 256) {
            int ll = i >> 6;
            float sum = 0.0f;
#pragma unroll
            for (int w = 0; w < NWARP_; w++) sum += ks[w * (L_ * HD_) + i];
            qs[i] = sum / Zg[ll];
        }
        __syncthreads();
    }

    for (int i = t; i < L_ * HD_; i += 256) {
        int ll = i >> 6, dd = i & 63;
        qout[((long)b * L_ + ll) * C_ + h * HD_ + dd] = qs[i];
    }
}

// ---------------------------------------------------------------------------
// Launch
// ---------------------------------------------------------------------------
extern "C" void kernel_launch(void* const* d_in, const int* in_sizes, int n_in,
                              void* d_out, int out_size)
{
    const float* x     = (const float*)d_in[0];
    const float* query = (const float*)d_in[1];
    const float* Wq    = (const float*)d_in[2];
    const float* Wk    = (const float*)d_in[3];
    const float* Wv    = (const float*)d_in[4];
    const float* Wproj = (const float*)d_in[5];
    const float* bproj = (const float*)d_in[6];
    float* out = (float*)d_out;

    float *k_scr, *q0_scr, *qf_scr, *tmp_scr;
    __nv_bfloat16 *xh, *xl, *wh, *wl;
    cudaGetSymbolAddress((void**)&k_scr,  g_k_scr);
    cudaGetSymbolAddress((void**)&q0_scr, g_q0_scr);
    cudaGetSymbolAddress((void**)&qf_scr, g_qf_scr);
    cudaGetSymbolAddress((void**)&tmp_scr, g_tmp_scr);
    cudaGetSymbolAddress((void**)&xh, g_xh);
    cudaGetSymbolAddress((void**)&xl, g_xl);
    cudaGetSymbolAddress((void**)&wh, g_wh);
    cudaGetSymbolAddress((void**)&wl, g_wl);

    static bool attr_set = false;
    if (!attr_set) {
        cudaFuncSetAttribute(k_gemm_mma, cudaFuncAttributeMaxDynamicSharedMemorySize,
                             GEMM_SMEM_REQ);
        attr_set = true;
    }

    // split/convert x and Wk into row-major bf16 hi/lo
    {
        int nch_x = (MROWS_ * C_) / 8;
        convert_split_kernel<<<(nch_x + 255) / 256, 256>>>(x, xh, xl, nch_x);
        int nch_w = (C_ * C_) / 8;
        convert_split_kernel<<<(nch_w + 255) / 256, 256>>>(Wk, wh, wl, nch_w);
    }
    // q0 = query @ Wq^T
    small_gemm_nt<<<dim3(C_ / 64, 1), 256>>>(query, Wq, nullptr, q0_scr, L_, C_, C_);
    // k = x @ Wk^T via HMMA (3-term bf16 split)
    k_gemm_mma<<<dim3(C_ / 128, MROWS_ / 128), 256, GEMM_SMEM_REQ>>>(xh, xl, wh, wl, k_scr);
    // 3-step Hopfield attention
    hopfield_kernel<<<B_ * H_, 256>>>(q0_scr, k_scr, qf_scr);
    // out projections
    small_gemm_nt<<<dim3(C_ / 64, (B_ * L_) / 16), 256>>>(
        qf_scr, Wv, nullptr, tmp_scr, B_ * L_, C_, C_);
    small_gemm_nt<<<dim3(C_ / 64, (B_ * L_) / 16), 256>>>(
        tmp_scr, Wproj, bproj, out, B_ * L_, C_, C_);
}